// round 13
// baseline (speedup 1.0000x reference)
#include <cuda_runtime.h>
#include <cuda_bf16.h>
#include <cstddef>
#include <cstdint>

// Depthwise cross-correlation — R13: swapped-accumulator fp32x2 pairing.
//   out[ch, oy, ox] = sum_{ky,kx} x[ch, oy+ky, ox+kx] * z[ch, ky, kx]
//   32768 channels, x: 31x31, z: 7x7, out: 25x25 (VALID, no flip)
//
// f32x2 lanes = output columns (2l, 2l+1). Two accumulators per ring slot:
//   A = (out0, out1): ffma2 with even-tap dups   (z2j , z2j )
//   B = (out1, out0): ffma2 with odd-tap pairs   (z2j-1, z2j+1)   [swapped!]
//   + 2 scalar FFMAs for the leftover terms w1*z1 (->out0), w6*z5 (->out1)
// => 14 MACs in 7 FMA issues per ky, every multiplicand a native LDS.64 pair
// (zero pair-building MOVs, zero padded-FMA waste). Cross-fold at store:
//   out0 = A.x + B.y ; out1 = A.y + B.x.
// SMEM x re-laid out at stage time: row pitch 32, channel pitch 992, so every
// window load is an aligned LDS.64 for every row parity.

#define NCHAN   32768
#define HX      31
#define HZ      7
#define HO      25
#define XSZ     961
#define ZSZ     49
#define OSZ     625
#define CPG     8                   // channels per group (2 per warp)
#define THREADS 128
#define CTAS_PER_SM 3
#define GRID    (152 * CTAS_PER_SM) // 456
#define NGROUPS (NCHAN / CPG)       // 4096 exactly
#define XTOT    ((size_t)NCHAN * XSZ)

#define CHP     992                 // smem channel pitch (31 rows x 32 floats)
#define GXS     (CPG * CHP)         // 7936 floats per x buffer
#define GXF     (CPG * XSZ)         // 7688 gmem floats per group
#define GZ_FLOATS (CPG * ZSZ)       // 392
#define GZ_V4     (GZ_FLOATS / 4)   // 98

__device__ __forceinline__ void ffma2(float2& d, const float2& a, const float2& b) {
    asm("fma.rn.f32x2 %0, %1, %2, %0;"
        : "+l"(reinterpret_cast<unsigned long long&>(d))
        : "l"(reinterpret_cast<const unsigned long long&>(a)),
          "l"(reinterpret_cast<const unsigned long long&>(b)));
}

__device__ __forceinline__ void cpasync4(uint32_t saddr, const void* gaddr) {
    asm volatile("cp.async.ca.shared.global [%0], [%1], 4;"
                 :: "r"(saddr), "l"(gaddr) : "memory");
}
__device__ __forceinline__ void cpasync16(uint32_t saddr, const void* gaddr) {
    asm volatile("cp.async.cg.shared.global [%0], [%1], 16;"
                 :: "r"(saddr), "l"(gaddr) : "memory");
}
#define CP_COMMIT() asm volatile("cp.async.commit_group;" ::: "memory")
#define CP_WAIT1()  asm volatile("cp.async.wait_group 1;" ::: "memory")
#define CP_WAIT0()  asm volatile("cp.async.wait_group 0;" ::: "memory")

// Stage group g: gmem rows of 31 floats -> smem rows of 32 (col 31 = junk pad,
// never used by kept lanes). Warp w stages channels 2w (lanes 0-15) and 2w+1
// (lanes 16-31); both 4B streams are fully coalesced 64B segments.
template <bool CLAMP>
__device__ __forceinline__ void prefetch_group(
    int g, float* xs, float* zs,
    const float* __restrict__ x, const float* __restrict__ z,
    int tid)
{
    const int warp = tid >> 5, lane = tid & 31;
    const int h = lane >> 4, l16 = lane & 15;
    const int ch = 2 * warp + h;                       // 0..7

    const float* gsrc = x + (size_t)g * GXF + ch * XSZ + l16;
    uint32_t sdst = (uint32_t)__cvta_generic_to_shared(xs + ch * CHP + l16);
    const float* xlim = x + (XTOT - 1);

    #pragma unroll
    for (int m = 0; m < HX; ++m) {
        cpasync4(sdst, gsrc);
        const float* g2 = gsrc + 16;                   // cols 16..31 (31 = pad)
        if (CLAMP && g2 > xlim) g2 = xlim;             // final-group tail only
        cpasync4(sdst + 64u, g2);
        gsrc += HX;                                    // next gmem row (31)
        sdst += 128u;                                  // next smem row (32)
    }

    if (tid < GZ_V4) {
        const float4* gz = reinterpret_cast<const float4*>(z) + (size_t)g * GZ_V4;
        const uint32_t sz = (uint32_t)__cvta_generic_to_shared(zs);
        cpasync16(sz + (uint32_t)tid * 16u, gz + tid);
    }
}

__device__ __forceinline__ void compute_group(
    int g, const float* __restrict__ xs, const float* __restrict__ zs,
    float* __restrict__ out, int lch, int l, bool active, bool store_hi)
{
    if (!active) return;                 // lanes 13..15 of each half-warp idle

    const float* xc = xs + lch * CHP;
    const float* zc = zs + lch * ZSZ;

    // Taps: per ky, 4 even-dup pairs + 2 odd pairs = 12 regs (84 total).
    float2 kA[HZ][4];
    float2 kB[HZ][2];
    #pragma unroll
    for (int ky = 0; ky < HZ; ++ky) {
        const float z0 = zc[7*ky+0], z1 = zc[7*ky+1], z2 = zc[7*ky+2],
                    z3 = zc[7*ky+3], z4 = zc[7*ky+4], z5 = zc[7*ky+5],
                    z6 = zc[7*ky+6];
        kA[ky][0] = make_float2(z0, z0);
        kA[ky][1] = make_float2(z2, z2);
        kA[ky][2] = make_float2(z4, z4);
        kA[ky][3] = make_float2(z6, z6);
        kB[ky][0] = make_float2(z1, z3);
        kB[ky][1] = make_float2(z3, z5);
    }

    // Ring of 7 slots, two pair-accumulators each (A straight, B swapped).
    float2 A[HZ], B[HZ];
    #pragma unroll
    for (int i = 0; i < HZ; ++i) {
        A[i] = make_float2(0.0f, 0.0f);
        B[i] = make_float2(0.0f, 0.0f);
    }

    // Window: 4 aligned LDS.64 per row (row pitch 32 floats = 16 float2).
    const float2* xb = reinterpret_cast<const float2*>(xc + 2 * l);
    float* go = out + (size_t)(g * CPG + lch) * OSZ + 2 * l;

    #pragma unroll
    for (int r = 0; r < HX; ++r) {
        const float2 P0 = xb[r * 16 + 0];   // (w0, w1)
        const float2 P1 = xb[r * 16 + 1];   // (w2, w3)
        const float2 P2 = xb[r * 16 + 2];   // (w4, w5)
        const float2 P3 = xb[r * 16 + 3];   // (w6, w7)  w7: pad, dead lanes only

        #pragma unroll
        for (int ky = 0; ky < HZ; ++ky) {
            const int oy = r - ky;
            if (oy >= 0 && oy < HO) {
                const int s = oy % HZ;                 // const after unroll
                ffma2(A[s], P0, kA[ky][0]);            // w0z0->o0 | w1z0->o1
                ffma2(A[s], P1, kA[ky][1]);            // w2z2->o0 | w3z2->o1
                ffma2(A[s], P2, kA[ky][2]);            // w4z4->o0 | w5z4->o1
                ffma2(A[s], P3, kA[ky][3]);            // w6z6->o0 | w7z6->o1(dead)
                ffma2(B[s], P1, kB[ky][0]);            // w2z1->o1 | w3z3->o0
                ffma2(B[s], P2, kB[ky][1]);            // w4z3->o1 | w5z5->o0
                B[s].y = fmaf(P0.y, kB[ky][0].x, B[s].y); // w1*z1 -> o0
                B[s].x = fmaf(P3.x, kB[ky][1].y, B[s].x); // w6*z5 -> o1
            }
        }

        if (r >= HZ - 1) {                             // output row r-6 done
            const int oy = r - (HZ - 1);
            const int s  = oy % HZ;
            go[oy * HO] = A[s].x + B[s].y;
            if (store_hi) go[oy * HO + 1] = A[s].y + B[s].x;
            A[s] = make_float2(0.0f, 0.0f);
            B[s] = make_float2(0.0f, 0.0f);
        }
    }
}

__global__ __launch_bounds__(THREADS, CTAS_PER_SM)
void dwxcorr_swap(const float* __restrict__ z,
                  const float* __restrict__ x,
                  float* __restrict__ out) {
    extern __shared__ float smem[];
    float* xb0 = smem;
    float* xb1 = smem + GXS;
    float* zb0 = smem + 2 * GXS;
    float* zb1 = zb0 + GZ_FLOATS;

    const int tid  = threadIdx.x;
    const int warp = tid >> 5;
    const int lane = tid & 31;
    const int h    = lane >> 4;          // half-warp: channel select
    const int l    = lane & 15;          // lane within half-warp
    const int lch  = 2 * warp + h;       // local channel 0..7
    const bool active   = (l <= 12);     // 13 col-pair slots cover 25 columns
    const bool store_hi = (l < 12);      // lane 12: column 24 only

    int g = blockIdx.x;
    if (g < NGROUPS) {
        if (g == NGROUPS - 1) prefetch_group<true >(g, xb0, zb0, x, z, tid);
        else                  prefetch_group<false>(g, xb0, zb0, x, z, tid);
    }
    CP_COMMIT();

    int i = 0;
    for (; g < NGROUPS; g += GRID, ++i) {
        float* xc = (i & 1) ? xb1 : xb0;
        float* zc = (i & 1) ? zb1 : zb0;
        float* xn = (i & 1) ? xb0 : xb1;
        float* zn = (i & 1) ? zb0 : zb1;

        const int gn = g + GRID;
        if (gn < NGROUPS) {
            if (gn == NGROUPS - 1) prefetch_group<true >(gn, xn, zn, x, z, tid);
            else                   prefetch_group<false>(gn, xn, zn, x, z, tid);
            CP_COMMIT();
            CP_WAIT1();                               // current group landed
        } else {
            CP_WAIT0();
        }
        __syncthreads();

        compute_group(g, xc, zc, out, lch, l, active, store_hi);

        __syncthreads();                              // done reading xc/zc
    }
}

extern "C" void kernel_launch(void* const* d_in, const int* in_sizes, int n_in,
                              void* d_out, int out_size) {
    // metadata order: d_in[0] = z_f [128,256,7,7], d_in[1] = x_f [128,256,31,31]
    const float* z = (const float*)d_in[0];
    const float* x = (const float*)d_in[1];
    float* out = (float*)d_out;

    const size_t smem = (size_t)(2 * GXS + 2 * GZ_FLOATS) * sizeof(float); // 66624 B
    cudaFuncSetAttribute(dwxcorr_swap,
                         cudaFuncAttributeMaxDynamicSharedMemorySize, (int)smem);
    dwxcorr_swap<<<GRID, THREADS, smem>>>(z, x, out);
}

// round 14
// speedup vs baseline: 1.0781x; 1.0781x over previous
#include <cuda_runtime.h>
#include <cuda_bf16.h>
#include <cstddef>
#include <cstdint>

// Depthwise cross-correlation — R14: R12 compute (output-column-paired fp32x2,
// q-pairs via MOV) + higher occupancy (7 CTAs/SM x 64 thr) + row-ahead LDS
// software pipelining.
//   out[ch, oy, ox] = sum_{ky,kx} x[ch, oy+ky, ox+kx] * z[ch, ky, kx]
//   32768 channels, x: 31x31, z: 7x7, out: 25x25 (VALID, no flip)

#define NCHAN   32768
#define HX      31
#define HZ      7
#define HO      25
#define XSZ     961
#define ZSZ     49
#define OSZ     625
#define CPG     4                   // channels per group (2 per warp)
#define THREADS 64
#define CTAS_PER_SM 7
#define GRID    (152 * CTAS_PER_SM) // 1064
#define NGROUPS (NCHAN / CPG)       // 8192 exactly, no tail

#define GX_FLOATS (CPG * XSZ)       // 3844 (15376 B, 16B-multiple)
#define GX_PAD    (GX_FLOATS + 4)   // lane-12 window overrun slack
#define GZ_FLOATS (CPG * ZSZ)       // 196 (784 B, 16B-multiple)
#define GX_V4     (GX_FLOATS / 4)   // 961
#define GZ_V4     (GZ_FLOATS / 4)   // 49

__device__ __forceinline__ void ffma2(float2& d, const float2& a, const float2& b) {
    asm("fma.rn.f32x2 %0, %1, %2, %0;"
        : "+l"(reinterpret_cast<unsigned long long&>(d))
        : "l"(reinterpret_cast<const unsigned long long&>(a)),
          "l"(reinterpret_cast<const unsigned long long&>(b)));
}

__device__ __forceinline__ void cpasync16(uint32_t saddr, const void* gaddr) {
    asm volatile("cp.async.cg.shared.global [%0], [%1], 16;"
                 :: "r"(saddr), "l"(gaddr) : "memory");
}
#define CP_COMMIT() asm volatile("cp.async.commit_group;" ::: "memory")
#define CP_WAIT1()  asm volatile("cp.async.wait_group 1;" ::: "memory")
#define CP_WAIT0()  asm volatile("cp.async.wait_group 0;" ::: "memory")

__device__ __forceinline__ void prefetch_group(
    int g, float* xs, float* zs,
    const float* __restrict__ x, const float* __restrict__ z, int tid)
{
    const float4* gx = reinterpret_cast<const float4*>(x) + (size_t)g * GX_V4;
    const float4* gz = reinterpret_cast<const float4*>(z) + (size_t)g * GZ_V4;
    const uint32_t sx = (uint32_t)__cvta_generic_to_shared(xs);
    const uint32_t sz = (uint32_t)__cvta_generic_to_shared(zs);
    #pragma unroll
    for (int j = tid; j < GX_V4; j += THREADS)     // ~15 per thread
        cpasync16(sx + (uint32_t)j * 16u, gx + j);
    if (tid < GZ_V4)
        cpasync16(sz + (uint32_t)tid * 16u, gz + tid);
}

__device__ __forceinline__ void compute_group(
    int g, const float* __restrict__ xs, const float* __restrict__ zs,
    float* __restrict__ out, int lch, int l, bool active, bool store_hi)
{
    if (!active) return;                 // lanes 13..15 of each half-warp idle

    const float* xc = xs + lch * XSZ;
    const float* zc = zs + lch * ZSZ;
    const int col0 = 2 * l;              // output columns (col0, col0+1)

    // Taps duplicated into both f32x2 lanes: 49 float2 (98 regs), broadcast LDS.
    float2 kt[ZSZ];
    #pragma unroll
    for (int j = 0; j < ZSZ; ++j) {
        const float zv = zc[j];
        kt[j] = make_float2(zv, zv);
    }

    // Ring of 7 accumulators; lanes = the two adjacent output columns.
    float2 acc[HZ];
    #pragma unroll
    for (int i = 0; i < HZ; ++i) acc[i] = make_float2(0.0f, 0.0f);

    const float* xb = xc + col0;
    float* go = out + (size_t)(g * CPG + lch) * OSZ + col0;

    // Row-ahead software pipeline: wn holds row r+1 while row r computes.
    float w[8];
    #pragma unroll
    for (int c = 0; c < 8; ++c) w[c] = xb[c];

    #pragma unroll
    for (int r = 0; r < HX; ++r) {
        float wn[8];
        if (r + 1 < HX) {
            #pragma unroll
            for (int c = 0; c < 8; ++c) wn[c] = xb[(r + 1) * HX + c];
        }

        const float2 p0 = make_float2(w[0], w[1]);   // even pairs: free
        const float2 p1 = make_float2(w[2], w[3]);
        const float2 p2 = make_float2(w[4], w[5]);
        const float2 p3 = make_float2(w[6], w[7]);
        const float2 q0 = make_float2(w[1], w[2]);   // odd pairs: MOV-built
        const float2 q1 = make_float2(w[3], w[4]);
        const float2 q2 = make_float2(w[5], w[6]);

        #pragma unroll
        for (int ky = 0; ky < HZ; ++ky) {
            const int oy = r - ky;
            if (oy >= 0 && oy < HO) {
                const int s = oy % HZ;               // const after unroll
                const float2* kz = &kt[ky * HZ];
                ffma2(acc[s], p0, kz[0]);            // kx=0: (x[c0],   x[c0+1])
                ffma2(acc[s], q0, kz[1]);            // kx=1: (x[c0+1], x[c0+2])
                ffma2(acc[s], p1, kz[2]);
                ffma2(acc[s], q1, kz[3]);
                ffma2(acc[s], p2, kz[4]);
                ffma2(acc[s], q2, kz[5]);
                ffma2(acc[s], p3, kz[6]);            // kx=6: (x[c0+6], x[c0+7])
            }
        }

        if (r >= HZ - 1) {                           // output row r-6 complete
            const int oy = r - (HZ - 1);
            const int s  = oy % HZ;
            go[oy * HO] = acc[s].x;
            if (store_hi) go[oy * HO + 1] = acc[s].y;
            acc[s] = make_float2(0.0f, 0.0f);
        }

        #pragma unroll
        for (int c = 0; c < 8; ++c) w[c] = wn[c];    // rename, no real MOVs
    }
}

__global__ __launch_bounds__(THREADS, CTAS_PER_SM)
void dwxcorr_op2b(const float* __restrict__ z,
                  const float* __restrict__ x,
                  float* __restrict__ out) {
    extern __shared__ float smem[];
    float* xb0 = smem;
    float* xb1 = smem + GX_PAD;
    float* zb0 = smem + 2 * GX_PAD;
    float* zb1 = zb0 + GZ_FLOATS;

    const int tid  = threadIdx.x;
    const int warp = tid >> 5;
    const int lane = tid & 31;
    const int h    = lane >> 4;          // half-warp: channel select
    const int l    = lane & 15;          // lane within half-warp
    const int lch  = 2 * warp + h;       // local channel 0..3
    const bool active   = (l <= 12);     // 13 column-pair slots cover 25 cols
    const bool store_hi = (l < 12);      // lane 12: column 24 only

    int g = blockIdx.x;
    if (g < NGROUPS)
        prefetch_group(g, xb0, zb0, x, z, tid);
    CP_COMMIT();

    int i = 0;
    for (; g < NGROUPS; g += GRID, ++i) {
        float* xc = (i & 1) ? xb1 : xb0;
        float* zc = (i & 1) ? zb1 : zb0;
        float* xn = (i & 1) ? xb0 : xb1;
        float* zn = (i & 1) ? zb0 : zb1;

        const int gn = g + GRID;
        if (gn < NGROUPS) {
            prefetch_group(gn, xn, zn, x, z, tid);   // background fill
            CP_COMMIT();
            CP_WAIT1();                               // current group landed
        } else {
            CP_WAIT0();
        }
        __syncthreads();

        compute_group(g, xc, zc, out, lch, l, active, store_hi);

        __syncthreads();                              // done reading xc/zc
    }
}

extern "C" void kernel_launch(void* const* d_in, const int* in_sizes, int n_in,
                              void* d_out, int out_size) {
    // metadata order: d_in[0] = z_f [128,256,7,7], d_in[1] = x_f [128,256,31,31]
    const float* z = (const float*)d_in[0];
    const float* x = (const float*)d_in[1];
    float* out = (float*)d_out;

    const size_t smem = (size_t)(2 * GX_PAD + 2 * GZ_FLOATS) * sizeof(float); // 32352 B
    cudaFuncSetAttribute(dwxcorr_op2b,
                         cudaFuncAttributeMaxDynamicSharedMemorySize, (int)smem);
    cudaFuncSetAttribute(dwxcorr_op2b,
                         cudaFuncAttributePreferredSharedMemoryCarveout, 100);
    dwxcorr_op2b<<<GRID, THREADS, smem>>>(z, x, out);
}